// round 14
// baseline (speedup 1.0000x reference)
#include <cuda_runtime.h>
#include <cuda_fp16.h>
#include <cstdint>
#include <cstddef>

// ---------------- problem constants ----------------
#define MM   8192
#define NN   1024
#define KK   4096
#define BM   128
#define BN   128
#define BK   64          // halves per k-iter
#define KIT  64          // KK / BK
#define STGS 3           // 3-stage ring -> 96KB smem -> 2 CTAs/SM
#define GTHREADS 128     // 4 warps, warp tile 64x64

// ---------------- scratch: __device__ globals (no runtime alloc) ----------------
static __device__ __half g_A[(size_t)MM * KK];        // fp16 hidden          (64 MB)
static __device__ __half g_S[(size_t)NN * KK];        // sign(W) in fp16      (8 MB)
static __device__ float  g_alpha[NN];
static __device__ float  g_temp[(size_t)MM * NN];     // x pre-LN (h + b)     (32 MB)

// smem: 3 stages x (A 16KB + B 16KB) = 96KB (+1KB alignment slack)
#define STAGE_A_BYTES (BM * 128)              // 16384
#define STAGE_BYTES   ((BM + BN) * 128)       // 32768
#define SMEM_DYN (STGS * STAGE_BYTES + 1024)

// ---------------- PTX helpers (base sm_103 ISA only) ----------------
__device__ __forceinline__ uint32_t smem_u32(const void* p) {
    uint32_t a;
    asm("{ .reg .u64 t; cvta.to.shared.u64 t, %1; cvt.u32.u64 %0, t; }" : "=r"(a) : "l"(p));
    return a;
}
#define CP16(dst, src)  asm volatile("cp.async.cg.shared.global [%0], [%1], 16;" :: "r"(dst), "l"(src) : "memory")
#define CP_COMMIT()     asm volatile("cp.async.commit_group;" ::: "memory")
#define CP_WAIT1()      asm volatile("cp.async.wait_group 1;" ::: "memory")
#define SW128(x)        ((x) ^ (((x) >> 3) & 0x70))

#define LDSM_X4(r0, r1, r2, r3, addr)                                         \
    asm volatile("ldmatrix.sync.aligned.m8n8.x4.shared.b16 {%0,%1,%2,%3}, [%4];" \
                 : "=r"(r0), "=r"(r1), "=r"(r2), "=r"(r3) : "r"(addr))

#define MMA16816(c, a, b)                                                     \
    asm volatile("mma.sync.aligned.m16n8k16.row.col.f32.f16.f16.f32 "         \
                 "{%0,%1,%2,%3}, {%4,%5,%6,%7}, {%8,%9}, {%0,%1,%2,%3};"      \
                 : "+f"((c)[0]), "+f"((c)[1]), "+f"((c)[2]), "+f"((c)[3])     \
                 : "r"((a)[0]), "r"((a)[1]), "r"((a)[2]), "r"((a)[3]),        \
                   "r"((b)[0]), "r"((b)[1]))

// ---------------- fused prep: blocks [0,1024) binarize W row; rest convert hidden ----------------
#define CONV_BLOCKS 32768   // MM*KK/4/256
__global__ void __launch_bounds__(256) prep_kernel(const float* __restrict__ W,
                                                   const float* __restrict__ h) {
    const int tid = threadIdx.x;
    if (blockIdx.x < NN) {
        // ---- weight row: alpha + sign ----
        const int o = blockIdx.x;
        const float* wr = W + (size_t)o * KK;
        float s = 0.f;
        const float4* w4 = (const float4*)wr;
        #pragma unroll
        for (int j = tid; j < KK / 4; j += 256) {
            float4 v = w4[j];
            s += fabsf(v.x) + fabsf(v.y) + fabsf(v.z) + fabsf(v.w);
        }
        #pragma unroll
        for (int off = 16; off; off >>= 1) s += __shfl_xor_sync(0xFFFFFFFFu, s, off);
        __shared__ float red[8];
        if ((tid & 31) == 0) red[tid >> 5] = s;
        __syncthreads();
        if (tid == 0) {
            float t = 0.f;
            #pragma unroll
            for (int i = 0; i < 8; ++i) t += red[i];
            g_alpha[o] = t * (1.0f / (float)KK);
        }
        const __half hp = __float2half(1.0f), hn = __float2half(-1.0f), hz = __float2half(0.0f);
        __half2* srow = (__half2*)(g_S + (size_t)o * KK);
        const float2* w2 = (const float2*)wr;
        #pragma unroll
        for (int j = tid; j < KK / 2; j += 256) {
            float2 v = w2[j];
            __half a = (v.x > 0.f) ? hp : ((v.x < 0.f) ? hn : hz);
            __half b = (v.y > 0.f) ? hp : ((v.y < 0.f) ? hn : hz);
            srow[j] = __halves2half2(a, b);
        }
    } else {
        // ---- hidden fp32 -> fp16 ----
        size_t i = (size_t)(blockIdx.x - NN) * 256 + tid;   // float4 index
        float4 v = ((const float4*)h)[i];
        __half2 lo = __floats2half2_rn(v.x, v.y);
        __half2 hi = __floats2half2_rn(v.z, v.w);
        uint2 pk;
        pk.x = *reinterpret_cast<uint32_t*>(&lo);
        pk.y = *reinterpret_cast<uint32_t*>(&hi);
        ((uint2*)g_A)[i] = pk;
    }
}

// ---------------- GEMM: 128x128x64 tiles, 4 warps, warp tile 64x64, 2 CTAs/SM ----------------
__device__ __forceinline__ void load_stage(uint32_t sbase, const __half* A,
                                           const __half* B, int kh0, int tid) {
    const uint32_t sa = sbase;
    const uint32_t sb = sbase + STAGE_A_BYTES;
    // A tile: 128 rows x 128B, 1024 granules of 16B, 8 per thread
    #pragma unroll
    for (int r = 0; r < 8; ++r) {
        int g = tid + r * GTHREADS;
        int row = g >> 3, gc = g & 7;
        CP16(sa + SW128((uint32_t)(row * 128 + gc * 16)),
             A + (size_t)row * KK + kh0 + gc * 8);
    }
    // B tile: 128 rows x 128B, 8 per thread
    #pragma unroll
    for (int r = 0; r < 8; ++r) {
        int g = tid + r * GTHREADS;
        int row = g >> 3, gc = g & 7;
        CP16(sb + SW128((uint32_t)(row * 128 + gc * 16)),
             B + (size_t)row * KK + kh0 + gc * 8);
    }
}

__global__ void __launch_bounds__(GTHREADS, 2) gemm_bin_kernel(const float* __restrict__ bias) {
    extern __shared__ char smraw[];
    uint32_t sb0 = smem_u32(smraw);
    uint32_t sbase = (sb0 + 1023u) & ~1023u;   // 1024B-align stage area

    const int tid = threadIdx.x, lane = tid & 31, wid = tid >> 5;
    const int wm = wid & 1;        // 2 warp rows  (M: 64 each)
    const int wn = wid >> 1;       // 2 warp cols  (N: 64 each)
    const int mtile = blockIdx.y * BM;   // gridDim.y = 64
    const int ntile = blockIdx.x * BN;   // gridDim.x = 8 (n fast -> A tile shared via L2)

    const __half* Abase = g_A + (size_t)mtile * KK;
    const __half* Bbase = g_S + (size_t)ntile * KK;

    // ldmatrix byte offsets (relative to stage tile base, before k-step col)
    uint32_t aoff[4];
    #pragma unroll
    for (int f = 0; f < 4; ++f)
        aoff[f] = (uint32_t)((wm * 64 + f * 16 + (lane & 15)) * 128 + ((lane >> 4) & 1) * 16);
    uint32_t boff[4];
    #pragma unroll
    for (int p = 0; p < 4; ++p)
        boff[p] = (uint32_t)((wn * 64 + p * 16 + (lane & 7) + ((lane >> 4) & 1) * 8) * 128
                             + ((lane >> 3) & 1) * 16);

    float acc[4][8][4];
    #pragma unroll
    for (int i = 0; i < 4; ++i)
        #pragma unroll
        for (int j = 0; j < 8; ++j)
            #pragma unroll
            for (int e = 0; e < 4; ++e) acc[i][j][e] = 0.f;

    // prologue: fill 2 stages
    load_stage(sbase + 0 * STAGE_BYTES, Abase, Bbase, 0, tid);
    CP_COMMIT();
    load_stage(sbase + 1 * STAGE_BYTES, Abase, Bbase, BK, tid);
    CP_COMMIT();

    int s_cur = 0, s_nxt = 2;   // stage indices mod 3
    for (int i = 0; i < KIT; ++i) {
        CP_WAIT1();            // stage i resident (<=1 group outstanding)
        __syncthreads();       // all warps done reading stage (i+2)%3 (== s_nxt)
        if (i + 2 < KIT)
            load_stage(sbase + s_nxt * STAGE_BYTES, Abase, Bbase, (i + 2) * BK, tid);
        CP_COMMIT();           // uniform group count even when empty

        const uint32_t sA = sbase + s_cur * STAGE_BYTES;
        const uint32_t sB = sA + STAGE_A_BYTES;
        #pragma unroll
        for (int ks = 0; ks < 4; ++ks) {
            uint32_t a[4][4], b[8][2];
            #pragma unroll
            for (int f = 0; f < 4; ++f) {
                uint32_t addr = sA + SW128(aoff[f] + ks * 32);
                LDSM_X4(a[f][0], a[f][1], a[f][2], a[f][3], addr);
            }
            #pragma unroll
            for (int p = 0; p < 4; ++p) {
                uint32_t r0, r1, r2, r3;
                uint32_t addr = sB + SW128(boff[p] + ks * 32);
                LDSM_X4(r0, r1, r2, r3, addr);
                b[2 * p][0] = r0;     b[2 * p][1] = r1;
                b[2 * p + 1][0] = r2; b[2 * p + 1][1] = r3;
            }
            #pragma unroll
            for (int mf = 0; mf < 4; ++mf)
                #pragma unroll
                for (int nf = 0; nf < 8; ++nf)
                    MMA16816(acc[mf][nf], a[mf], b[nf]);
        }
        s_cur = (s_cur == 2) ? 0 : s_cur + 1;
        s_nxt = (s_nxt == 2) ? 0 : s_nxt + 1;
    }

    // ---------------- epilogue: temp = alpha*acc + bias ----------------
    const int mbase = mtile + wm * 64 + (lane >> 2);
    const int nbase = ntile + wn * 64 + (lane & 3) * 2;
    #pragma unroll
    for (int nf = 0; nf < 8; ++nf) {
        const int n = nbase + nf * 8;
        const float2 al = *(const float2*)&g_alpha[n];
        const float2 bi = *(const float2*)&bias[n];
        #pragma unroll
        for (int mf = 0; mf < 4; ++mf) {
            const int m = mbase + mf * 16;
            float2 v0, v1;
            v0.x = fmaf(al.x, acc[mf][nf][0], bi.x);
            v0.y = fmaf(al.y, acc[mf][nf][1], bi.y);
            v1.x = fmaf(al.x, acc[mf][nf][2], bi.x);
            v1.y = fmaf(al.y, acc[mf][nf][3], bi.y);
            *(float2*)&g_temp[(size_t)m * NN + n] = v0;
            *(float2*)&g_temp[(size_t)(m + 8) * NN + n] = v1;
        }
    }
}

// ---------------- residual add + LayerNorm ----------------
__global__ void __launch_bounds__(256) ln_kernel(const float* __restrict__ inp,
                                                 const float* __restrict__ gamma,
                                                 const float* __restrict__ beta,
                                                 float* __restrict__ out) {
    const int row = blockIdx.x, tid = threadIdx.x;
    const float4 a = ((const float4*)(g_temp + (size_t)row * NN))[tid];
    const float4 b = ((const float4*)(inp + (size_t)row * NN))[tid];
    float4 x;
    x.x = a.x + b.x; x.y = a.y + b.y; x.z = a.z + b.z; x.w = a.w + b.w;
    float s = x.x + x.y + x.z + x.w;
    float q = x.x * x.x + x.y * x.y + x.z * x.z + x.w * x.w;
    #pragma unroll
    for (int o = 16; o; o >>= 1) {
        s += __shfl_xor_sync(0xFFFFFFFFu, s, o);
        q += __shfl_xor_sync(0xFFFFFFFFu, q, o);
    }
    __shared__ float ss[8], sq[8];
    if ((tid & 31) == 0) { ss[tid >> 5] = s; sq[tid >> 5] = q; }
    __syncthreads();
    if (tid < 32) {
        s = (tid < 8) ? ss[tid] : 0.f;
        q = (tid < 8) ? sq[tid] : 0.f;
        #pragma unroll
        for (int o = 4; o; o >>= 1) {
            s += __shfl_xor_sync(0xFFFFFFFFu, s, o);
            q += __shfl_xor_sync(0xFFFFFFFFu, q, o);
        }
        if (tid == 0) { ss[0] = s; sq[0] = q; }
    }
    __syncthreads();
    const float mu = ss[0] * (1.0f / (float)NN);
    const float var = sq[0] * (1.0f / (float)NN) - mu * mu;
    const float rs = rsqrtf(var + 1e-12f);
    const float4 g = ((const float4*)gamma)[tid];
    const float4 be = ((const float4*)beta)[tid];
    float4 o4;
    o4.x = g.x * (x.x - mu) * rs + be.x;
    o4.y = g.y * (x.y - mu) * rs + be.y;
    o4.z = g.z * (x.z - mu) * rs + be.z;
    o4.w = g.w * (x.w - mu) * rs + be.w;
    ((float4*)(out + (size_t)row * NN))[tid] = o4;
}

// ---------------- launch ----------------
extern "C" void kernel_launch(void* const* d_in, const int* in_sizes, int n_in,
                              void* d_out, int out_size) {
    (void)in_sizes; (void)n_in; (void)out_size;
    const float* hidden = (const float*)d_in[0];   // [16,512,4096]
    const float* input  = (const float*)d_in[1];   // [16,512,1024]
    const float* W      = (const float*)d_in[2];   // [1024,4096]
    const float* b      = (const float*)d_in[3];   // [1024]
    const float* gamma  = (const float*)d_in[4];   // [1024]
    const float* beta   = (const float*)d_in[5];   // [1024]
    float* out = (float*)d_out;

    cudaFuncSetAttribute(gemm_bin_kernel, cudaFuncAttributeMaxDynamicSharedMemorySize, SMEM_DYN);

    prep_kernel<<<NN + CONV_BLOCKS, 256>>>(W, hidden);
    gemm_bin_kernel<<<dim3(NN / BN, MM / BM), GTHREADS, SMEM_DYN>>>(b);
    ln_kernel<<<MM, 256>>>(input, gamma, beta, out);
}

// round 15
// speedup vs baseline: 1.0128x; 1.0128x over previous
#include <cuda_runtime.h>
#include <cuda_fp16.h>
#include <cstdint>
#include <cstddef>

// ---------------- problem constants ----------------
#define MM   8192
#define NN   1024
#define KK   4096
#define BM   128
#define BN   128
#define BK   64          // halves per k-iter
#define KIT  64          // KK / BK
#define STGS 3           // 3-stage ring -> 96KB smem -> 2 CTAs/SM

// ---------------- scratch: __device__ globals (no runtime alloc) ----------------
static __device__ __half g_A[(size_t)MM * KK];        // fp16 hidden          (64 MB)
static __device__ __half g_S[(size_t)NN * KK];        // sign(W) in fp16      (8 MB)
static __device__ float  g_alpha[NN];
static __device__ __half g_temp[(size_t)MM * NN];     // h + b in fp16        (16 MB)

// smem: 3 stages x (A 16KB + B 16KB) = 96KB (+1KB alignment slack)
#define STAGE_A_BYTES (BM * 128)              // 16384
#define STAGE_BYTES   ((BM + BN) * 128)       // 32768
#define SMEM_DYN (STGS * STAGE_BYTES + 1024)

// ---------------- PTX helpers (base sm_103 ISA only) ----------------
__device__ __forceinline__ uint32_t smem_u32(const void* p) {
    uint32_t a;
    asm("{ .reg .u64 t; cvta.to.shared.u64 t, %1; cvt.u32.u64 %0, t; }" : "=r"(a) : "l"(p));
    return a;
}
#define CP16(dst, src)  asm volatile("cp.async.cg.shared.global [%0], [%1], 16;" :: "r"(dst), "l"(src) : "memory")
#define CP_COMMIT()     asm volatile("cp.async.commit_group;" ::: "memory")
#define CP_WAIT1()      asm volatile("cp.async.wait_group 1;" ::: "memory")
#define SW128(x)        ((x) ^ (((x) >> 3) & 0x70))

#define LDSM_X4(r0, r1, r2, r3, addr)                                         \
    asm volatile("ldmatrix.sync.aligned.m8n8.x4.shared.b16 {%0,%1,%2,%3}, [%4];" \
                 : "=r"(r0), "=r"(r1), "=r"(r2), "=r"(r3) : "r"(addr))

#define MMA16816(c, a, b)                                                     \
    asm volatile("mma.sync.aligned.m16n8k16.row.col.f32.f16.f16.f32 "         \
                 "{%0,%1,%2,%3}, {%4,%5,%6,%7}, {%8,%9}, {%0,%1,%2,%3};"      \
                 : "+f"((c)[0]), "+f"((c)[1]), "+f"((c)[2]), "+f"((c)[3])     \
                 : "r"((a)[0]), "r"((a)[1]), "r"((a)[2]), "r"((a)[3]),        \
                   "r"((b)[0]), "r"((b)[1]))

// ---------------- fused prep: blocks [0,1024) binarize W row; rest convert hidden ----------------
#define CONV_BLOCKS 32768   // MM*KK/4/256
__global__ void __launch_bounds__(256) prep_kernel(const float* __restrict__ W,
                                                   const float* __restrict__ h) {
    const int tid = threadIdx.x;
    if (blockIdx.x < NN) {
        // ---- weight row: alpha + sign ----
        const int o = blockIdx.x;
        const float* wr = W + (size_t)o * KK;
        float s = 0.f;
        const float4* w4 = (const float4*)wr;
        #pragma unroll
        for (int j = tid; j < KK / 4; j += 256) {
            float4 v = w4[j];
            s += fabsf(v.x) + fabsf(v.y) + fabsf(v.z) + fabsf(v.w);
        }
        #pragma unroll
        for (int off = 16; off; off >>= 1) s += __shfl_xor_sync(0xFFFFFFFFu, s, off);
        __shared__ float red[8];
        if ((tid & 31) == 0) red[tid >> 5] = s;
        __syncthreads();
        if (tid == 0) {
            float t = 0.f;
            #pragma unroll
            for (int i = 0; i < 8; ++i) t += red[i];
            g_alpha[o] = t * (1.0f / (float)KK);
        }
        const __half hp = __float2half(1.0f), hn = __float2half(-1.0f), hz = __float2half(0.0f);
        __half2* srow = (__half2*)(g_S + (size_t)o * KK);
        const float2* w2 = (const float2*)wr;
        #pragma unroll
        for (int j = tid; j < KK / 2; j += 256) {
            float2 v = w2[j];
            __half a = (v.x > 0.f) ? hp : ((v.x < 0.f) ? hn : hz);
            __half b = (v.y > 0.f) ? hp : ((v.y < 0.f) ? hn : hz);
            srow[j] = __halves2half2(a, b);
        }
    } else {
        // ---- hidden fp32 -> fp16 ----
        size_t i = (size_t)(blockIdx.x - NN) * 256 + tid;   // float4 index
        float4 v = ((const float4*)h)[i];
        __half2 lo = __floats2half2_rn(v.x, v.y);
        __half2 hi = __floats2half2_rn(v.z, v.w);
        uint2 pk;
        pk.x = *reinterpret_cast<uint32_t*>(&lo);
        pk.y = *reinterpret_cast<uint32_t*>(&hi);
        ((uint2*)g_A)[i] = pk;
    }
}

// ---------------- GEMM: 128x128x64 tiles, warp tile 64x32, 2 CTAs/SM ----------------
__device__ __forceinline__ void load_stage(uint32_t sbase, const __half* A,
                                           const __half* B, int kh0, int tid) {
    const uint32_t sa = sbase;
    const uint32_t sb = sbase + STAGE_A_BYTES;
    // A tile: 128 rows x 128B, 1024 granules of 16B, 4 per thread
    #pragma unroll
    for (int r = 0; r < 4; ++r) {
        int g = tid + r * 256;
        int row = g >> 3, gc = g & 7;
        CP16(sa + SW128((uint32_t)(row * 128 + gc * 16)),
             A + (size_t)row * KK + kh0 + gc * 8);
    }
    // B tile: 128 rows x 128B
    #pragma unroll
    for (int r = 0; r < 4; ++r) {
        int g = tid + r * 256;
        int row = g >> 3, gc = g & 7;
        CP16(sb + SW128((uint32_t)(row * 128 + gc * 16)),
             B + (size_t)row * KK + kh0 + gc * 8);
    }
}

__global__ void __launch_bounds__(256, 2) gemm_bin_kernel(const float* __restrict__ bias) {
    extern __shared__ char smraw[];
    uint32_t sb0 = smem_u32(smraw);
    uint32_t sbase = (sb0 + 1023u) & ~1023u;   // 1024B-align stage area

    const int tid = threadIdx.x, lane = tid & 31, wid = tid >> 5;
    const int wm = wid & 1;        // 2 warp rows  (M: 64 each)
    const int wn = wid >> 1;       // 4 warp cols  (N: 32 each)
    const int mtile = blockIdx.y * BM;   // gridDim.y = 64
    const int ntile = blockIdx.x * BN;   // gridDim.x = 8 (n fast -> A tile shared via L2)

    const __half* Abase = g_A + (size_t)mtile * KK;
    const __half* Bbase = g_S + (size_t)ntile * KK;

    // ldmatrix byte offsets (relative to stage tile base, before k-step col)
    uint32_t aoff[4];
    #pragma unroll
    for (int f = 0; f < 4; ++f)
        aoff[f] = (uint32_t)((wm * 64 + f * 16 + (lane & 15)) * 128 + ((lane >> 4) & 1) * 16);
    uint32_t boff[2];
    #pragma unroll
    for (int p = 0; p < 2; ++p)
        boff[p] = (uint32_t)((wn * 32 + p * 16 + (lane & 7) + ((lane >> 4) & 1) * 8) * 128
                             + ((lane >> 3) & 1) * 16);

    float acc[4][4][4];
    #pragma unroll
    for (int i = 0; i < 4; ++i)
        #pragma unroll
        for (int j = 0; j < 4; ++j)
            #pragma unroll
            for (int e = 0; e < 4; ++e) acc[i][j][e] = 0.f;

    // prologue: fill 2 stages
    load_stage(sbase + 0 * STAGE_BYTES, Abase, Bbase, 0, tid);
    CP_COMMIT();
    load_stage(sbase + 1 * STAGE_BYTES, Abase, Bbase, BK, tid);
    CP_COMMIT();

    int s_cur = 0, s_nxt = 2;   // stage indices mod 3
    for (int i = 0; i < KIT; ++i) {
        CP_WAIT1();            // stage i resident (<=1 group outstanding)
        __syncthreads();       // all warps done reading stage (i+2)%3 (== s_nxt)
        if (i + 2 < KIT)
            load_stage(sbase + s_nxt * STAGE_BYTES, Abase, Bbase, (i + 2) * BK, tid);
        CP_COMMIT();           // uniform group count even when empty

        const uint32_t sA = sbase + s_cur * STAGE_BYTES;
        const uint32_t sB = sA + STAGE_A_BYTES;
        #pragma unroll
        for (int ks = 0; ks < 4; ++ks) {
            uint32_t a[4][4], b[4][2];
            #pragma unroll
            for (int f = 0; f < 4; ++f) {
                uint32_t addr = sA + SW128(aoff[f] + ks * 32);
                LDSM_X4(a[f][0], a[f][1], a[f][2], a[f][3], addr);
            }
            #pragma unroll
            for (int p = 0; p < 2; ++p) {
                uint32_t r0, r1, r2, r3;
                uint32_t addr = sB + SW128(boff[p] + ks * 32);
                LDSM_X4(r0, r1, r2, r3, addr);
                b[2 * p][0] = r0;     b[2 * p][1] = r1;
                b[2 * p + 1][0] = r2; b[2 * p + 1][1] = r3;
            }
            #pragma unroll
            for (int mf = 0; mf < 4; ++mf)
                #pragma unroll
                for (int nf = 0; nf < 4; ++nf)
                    MMA16816(acc[mf][nf], a[mf], b[nf]);
        }
        s_cur = (s_cur == 2) ? 0 : s_cur + 1;
        s_nxt = (s_nxt == 2) ? 0 : s_nxt + 1;
    }

    // ---------------- epilogue: temp = fp16(alpha*acc + bias) ----------------
    const int mbase = mtile + wm * 64 + (lane >> 2);
    const int nbase = ntile + wn * 32 + (lane & 3) * 2;
    #pragma unroll
    for (int nf = 0; nf < 4; ++nf) {
        const int n = nbase + nf * 8;
        const float2 al = *(const float2*)&g_alpha[n];
        const float2 bi = *(const float2*)&bias[n];
        #pragma unroll
        for (int mf = 0; mf < 4; ++mf) {
            const int m = mbase + mf * 16;
            __half2 h0 = __floats2half2_rn(fmaf(al.x, acc[mf][nf][0], bi.x),
                                           fmaf(al.y, acc[mf][nf][1], bi.y));
            __half2 h1 = __floats2half2_rn(fmaf(al.x, acc[mf][nf][2], bi.x),
                                           fmaf(al.y, acc[mf][nf][3], bi.y));
            *(__half2*)&g_temp[(size_t)m * NN + n] = h0;
            *(__half2*)&g_temp[(size_t)(m + 8) * NN + n] = h1;
        }
    }
}

// ---------------- residual add + LayerNorm: warp-per-row, no block barriers ----------------
#define LNROWS 8
__global__ void __launch_bounds__(256) ln_kernel(const float* __restrict__ inp,
                                                 const float* __restrict__ gamma,
                                                 const float* __restrict__ beta,
                                                 float* __restrict__ out) {
    const int lane = threadIdx.x & 31;
    const int row  = blockIdx.x * LNROWS + (threadIdx.x >> 5);

    const uint2*  t2 = (const uint2*)(g_temp + (size_t)row * NN);   // 4 halfs per uint2
    const float4* i4 = (const float4*)(inp + (size_t)row * NN);

    float4 x[8];
    float s = 0.f, q = 0.f;
    #pragma unroll
    for (int u = 0; u < 8; ++u) {
        const int idx = u * 32 + lane;        // float4 index within row (n = idx*4)
        uint2 hv = t2[idx];
        float2 f0 = __half22float2(*(__half2*)&hv.x);
        float2 f1 = __half22float2(*(__half2*)&hv.y);
        float4 r = i4[idx];
        x[u].x = f0.x + r.x; x[u].y = f0.y + r.y;
        x[u].z = f1.x + r.z; x[u].w = f1.y + r.w;
        s += x[u].x + x[u].y + x[u].z + x[u].w;
        q += x[u].x * x[u].x + x[u].y * x[u].y + x[u].z * x[u].z + x[u].w * x[u].w;
    }
    #pragma unroll
    for (int o = 16; o; o >>= 1) {
        s += __shfl_xor_sync(0xFFFFFFFFu, s, o);
        q += __shfl_xor_sync(0xFFFFFFFFu, q, o);
    }
    const float mu = s * (1.0f / (float)NN);
    const float var = q * (1.0f / (float)NN) - mu * mu;
    const float rs = rsqrtf(var + 1e-12f);

    float4* o4 = (float4*)(out + (size_t)row * NN);
    #pragma unroll
    for (int u = 0; u < 8; ++u) {
        const int idx = u * 32 + lane;
        const float4 g = ((const float4*)gamma)[idx];
        const float4 be = ((const float4*)beta)[idx];
        float4 v;
        v.x = g.x * (x[u].x - mu) * rs + be.x;
        v.y = g.y * (x[u].y - mu) * rs + be.y;
        v.z = g.z * (x[u].z - mu) * rs + be.z;
        v.w = g.w * (x[u].w - mu) * rs + be.w;
        o4[idx] = v;
    }
}

// ---------------- launch ----------------
extern "C" void kernel_launch(void* const* d_in, const int* in_sizes, int n_in,
                              void* d_out, int out_size) {
    (void)in_sizes; (void)n_in; (void)out_size;
    const float* hidden = (const float*)d_in[0];   // [16,512,4096]
    const float* input  = (const float*)d_in[1];   // [16,512,1024]
    const float* W      = (const float*)d_in[2];   // [1024,4096]
    const float* b      = (const float*)d_in[3];   // [1024]
    const float* gamma  = (const float*)d_in[4];   // [1024]
    const float* beta   = (const float*)d_in[5];   // [1024]
    float* out = (float*)d_out;

    cudaFuncSetAttribute(gemm_bin_kernel, cudaFuncAttributeMaxDynamicSharedMemorySize, SMEM_DYN);

    prep_kernel<<<NN + CONV_BLOCKS, 256>>>(W, hidden);
    gemm_bin_kernel<<<dim3(NN / BN, MM / BM), 256, SMEM_DYN>>>(b);
    ln_kernel<<<MM / LNROWS, 256>>>(input, gamma, beta, out);
}

// round 16
// speedup vs baseline: 1.0320x; 1.0189x over previous
#include <cuda_runtime.h>
#include <cuda_fp16.h>
#include <cstdint>
#include <cstddef>

// ---------------- problem constants ----------------
#define MM   8192
#define NN   1024
#define KK   4096
#define BM   128
#define BN   128
#define BK   64          // halves per k-iter
#define KIT  64          // KK / BK
#define STGS 3           // 3-stage ring -> 96KB smem -> 2 CTAs/SM

// ---------------- scratch: __device__ globals (no runtime alloc) ----------------
static __device__ __half g_A[(size_t)MM * KK];        // fp16 hidden          (64 MB)
static __device__ __half g_S[(size_t)NN * KK];        // sign(W) in fp16      (8 MB)
static __device__ float  g_alpha[NN];
static __device__ __half g_temp[(size_t)MM * NN];     // h + b in fp16        (16 MB)

// smem: 3 stages x (A 16KB + B 16KB) = 96KB (+1KB alignment slack)
#define STAGE_A_BYTES (BM * 128)              // 16384
#define STAGE_BYTES   ((BM + BN) * 128)       // 32768
#define SMEM_DYN (STGS * STAGE_BYTES + 1024)

// ---------------- PTX helpers (base sm_103 ISA only) ----------------
__device__ __forceinline__ uint32_t smem_u32(const void* p) {
    uint32_t a;
    asm("{ .reg .u64 t; cvta.to.shared.u64 t, %1; cvt.u32.u64 %0, t; }" : "=r"(a) : "l"(p));
    return a;
}
#define CP16(dst, src)  asm volatile("cp.async.cg.shared.global [%0], [%1], 16;" :: "r"(dst), "l"(src) : "memory")
#define CP_COMMIT()     asm volatile("cp.async.commit_group;" ::: "memory")
#define CP_WAIT1()      asm volatile("cp.async.wait_group 1;" ::: "memory")
#define SW128(x)        ((x) ^ (((x) >> 3) & 0x70))

#define LDSM_X4(r0, r1, r2, r3, addr)                                         \
    asm volatile("ldmatrix.sync.aligned.m8n8.x4.shared.b16 {%0,%1,%2,%3}, [%4];" \
                 : "=r"(r0), "=r"(r1), "=r"(r2), "=r"(r3) : "r"(addr))

#define MMA16816(c, a, b)                                                     \
    asm volatile("mma.sync.aligned.m16n8k16.row.col.f32.f16.f16.f32 "         \
                 "{%0,%1,%2,%3}, {%4,%5,%6,%7}, {%8,%9}, {%0,%1,%2,%3};"      \
                 : "+f"((c)[0]), "+f"((c)[1]), "+f"((c)[2]), "+f"((c)[3])     \
                 : "r"((a)[0]), "r"((a)[1]), "r"((a)[2]), "r"((a)[3]),        \
                   "r"((b)[0]), "r"((b)[1]))

// ---------------- fused prep: blocks [0,1024) binarize W row; rest convert hidden ----------------
// conv side: 4 independent float4 loads per thread (MLP=4) -> higher DRAM SOL
#define CONV_BLOCKS 8192   // MM*KK/4/256/4
__global__ void __launch_bounds__(256) prep_kernel(const float* __restrict__ W,
                                                   const float* __restrict__ h) {
    const int tid = threadIdx.x;
    if (blockIdx.x < NN) {
        // ---- weight row: alpha + sign ----
        const int o = blockIdx.x;
        const float* wr = W + (size_t)o * KK;
        float s = 0.f;
        const float4* w4 = (const float4*)wr;
        #pragma unroll
        for (int j = tid; j < KK / 4; j += 256) {
            float4 v = __ldcs(&w4[j]);
            s += fabsf(v.x) + fabsf(v.y) + fabsf(v.z) + fabsf(v.w);
        }
        #pragma unroll
        for (int off = 16; off; off >>= 1) s += __shfl_xor_sync(0xFFFFFFFFu, s, off);
        __shared__ float red[8];
        if ((tid & 31) == 0) red[tid >> 5] = s;
        __syncthreads();
        if (tid == 0) {
            float t = 0.f;
            #pragma unroll
            for (int i = 0; i < 8; ++i) t += red[i];
            g_alpha[o] = t * (1.0f / (float)KK);
        }
        const __half hp = __float2half(1.0f), hn = __float2half(-1.0f), hz = __float2half(0.0f);
        __half2* srow = (__half2*)(g_S + (size_t)o * KK);
        const float2* w2 = (const float2*)wr;
        #pragma unroll
        for (int j = tid; j < KK / 2; j += 256) {
            float2 v = __ldcs(&w2[j]);
            __half a = (v.x > 0.f) ? hp : ((v.x < 0.f) ? hn : hz);
            __half b = (v.y > 0.f) ? hp : ((v.y < 0.f) ? hn : hz);
            srow[j] = __halves2half2(a, b);
        }
    } else {
        // ---- hidden fp32 -> fp16, 4 float4 per thread ----
        const size_t base = (size_t)(blockIdx.x - NN) * 1024 + tid;   // float4 index
        const float4* h4 = (const float4*)h;
        float4 v[4];
        #pragma unroll
        for (int r = 0; r < 4; ++r) v[r] = __ldcs(&h4[base + r * 256]);
        #pragma unroll
        for (int r = 0; r < 4; ++r) {
            __half2 lo = __floats2half2_rn(v[r].x, v[r].y);
            __half2 hi = __floats2half2_rn(v[r].z, v[r].w);
            uint2 pk;
            pk.x = *reinterpret_cast<uint32_t*>(&lo);
            pk.y = *reinterpret_cast<uint32_t*>(&hi);
            ((uint2*)g_A)[base + r * 256] = pk;
        }
    }
}

// ---------------- GEMM: 128x128x64 tiles, warp tile 64x32, 2 CTAs/SM ----------------
__device__ __forceinline__ void load_stage(uint32_t sbase, const __half* A,
                                           const __half* B, int kh0, int tid) {
    const uint32_t sa = sbase;
    const uint32_t sb = sbase + STAGE_A_BYTES;
    // A tile: 128 rows x 128B, 1024 granules of 16B, 4 per thread
    #pragma unroll
    for (int r = 0; r < 4; ++r) {
        int g = tid + r * 256;
        int row = g >> 3, gc = g & 7;
        CP16(sa + SW128((uint32_t)(row * 128 + gc * 16)),
             A + (size_t)row * KK + kh0 + gc * 8);
    }
    // B tile: 128 rows x 128B
    #pragma unroll
    for (int r = 0; r < 4; ++r) {
        int g = tid + r * 256;
        int row = g >> 3, gc = g & 7;
        CP16(sb + SW128((uint32_t)(row * 128 + gc * 16)),
             B + (size_t)row * KK + kh0 + gc * 8);
    }
}

__global__ void __launch_bounds__(256, 2) gemm_bin_kernel(const float* __restrict__ bias) {
    extern __shared__ char smraw[];
    uint32_t sb0 = smem_u32(smraw);
    uint32_t sbase = (sb0 + 1023u) & ~1023u;   // 1024B-align stage area

    const int tid = threadIdx.x, lane = tid & 31, wid = tid >> 5;
    const int wm = wid & 1;        // 2 warp rows  (M: 64 each)
    const int wn = wid >> 1;       // 4 warp cols  (N: 32 each)
    const int mtile = blockIdx.y * BM;   // gridDim.y = 64
    const int ntile = blockIdx.x * BN;   // gridDim.x = 8 (n fast -> A tile shared via L2)

    const __half* Abase = g_A + (size_t)mtile * KK;
    const __half* Bbase = g_S + (size_t)ntile * KK;

    // ldmatrix byte offsets (relative to stage tile base, before k-step col)
    uint32_t aoff[4];
    #pragma unroll
    for (int f = 0; f < 4; ++f)
        aoff[f] = (uint32_t)((wm * 64 + f * 16 + (lane & 15)) * 128 + ((lane >> 4) & 1) * 16);
    uint32_t boff[2];
    #pragma unroll
    for (int p = 0; p < 2; ++p)
        boff[p] = (uint32_t)((wn * 32 + p * 16 + (lane & 7) + ((lane >> 4) & 1) * 8) * 128
                             + ((lane >> 3) & 1) * 16);

    float acc[4][4][4];
    #pragma unroll
    for (int i = 0; i < 4; ++i)
        #pragma unroll
        for (int j = 0; j < 4; ++j)
            #pragma unroll
            for (int e = 0; e < 4; ++e) acc[i][j][e] = 0.f;

    // prologue: fill 2 stages
    load_stage(sbase + 0 * STAGE_BYTES, Abase, Bbase, 0, tid);
    CP_COMMIT();
    load_stage(sbase + 1 * STAGE_BYTES, Abase, Bbase, BK, tid);
    CP_COMMIT();

    int s_cur = 0, s_nxt = 2;   // stage indices mod 3
    for (int i = 0; i < KIT; ++i) {
        CP_WAIT1();            // stage i resident (<=1 group outstanding)
        __syncthreads();       // all warps done reading stage (i+2)%3 (== s_nxt)
        if (i + 2 < KIT)
            load_stage(sbase + s_nxt * STAGE_BYTES, Abase, Bbase, (i + 2) * BK, tid);
        CP_COMMIT();           // uniform group count even when empty

        const uint32_t sA = sbase + s_cur * STAGE_BYTES;
        const uint32_t sB = sA + STAGE_A_BYTES;
        #pragma unroll
        for (int ks = 0; ks < 4; ++ks) {
            uint32_t a[4][4], b[4][2];
            #pragma unroll
            for (int f = 0; f < 4; ++f) {
                uint32_t addr = sA + SW128(aoff[f] + ks * 32);
                LDSM_X4(a[f][0], a[f][1], a[f][2], a[f][3], addr);
            }
            #pragma unroll
            for (int p = 0; p < 2; ++p) {
                uint32_t r0, r1, r2, r3;
                uint32_t addr = sB + SW128(boff[p] + ks * 32);
                LDSM_X4(r0, r1, r2, r3, addr);
                b[2 * p][0] = r0;     b[2 * p][1] = r1;
                b[2 * p + 1][0] = r2; b[2 * p + 1][1] = r3;
            }
            #pragma unroll
            for (int mf = 0; mf < 4; ++mf)
                #pragma unroll
                for (int nf = 0; nf < 4; ++nf)
                    MMA16816(acc[mf][nf], a[mf], b[nf]);
        }
        s_cur = (s_cur == 2) ? 0 : s_cur + 1;
        s_nxt = (s_nxt == 2) ? 0 : s_nxt + 1;
    }

    // ---------------- epilogue: temp = fp16(alpha*acc + bias) ----------------
    const int mbase = mtile + wm * 64 + (lane >> 2);
    const int nbase = ntile + wn * 32 + (lane & 3) * 2;
    #pragma unroll
    for (int nf = 0; nf < 4; ++nf) {
        const int n = nbase + nf * 8;
        const float2 al = *(const float2*)&g_alpha[n];
        const float2 bi = *(const float2*)&bias[n];
        #pragma unroll
        for (int mf = 0; mf < 4; ++mf) {
            const int m = mbase + mf * 16;
            __half2 h0 = __floats2half2_rn(fmaf(al.x, acc[mf][nf][0], bi.x),
                                           fmaf(al.y, acc[mf][nf][1], bi.y));
            __half2 h1 = __floats2half2_rn(fmaf(al.x, acc[mf][nf][2], bi.x),
                                           fmaf(al.y, acc[mf][nf][3], bi.y));
            *(__half2*)&g_temp[(size_t)m * NN + n] = h0;
            *(__half2*)&g_temp[(size_t)(m + 8) * NN + n] = h1;
        }
    }
}

// ---------------- residual add + LayerNorm: warp-per-row, no block barriers ----------------
#define LNROWS 8
__global__ void __launch_bounds__(256) ln_kernel(const float* __restrict__ inp,
                                                 const float* __restrict__ gamma,
                                                 const float* __restrict__ beta,
                                                 float* __restrict__ out) {
    const int lane = threadIdx.x & 31;
    const int row  = blockIdx.x * LNROWS + (threadIdx.x >> 5);

    const uint2*  t2 = (const uint2*)(g_temp + (size_t)row * NN);   // 4 halfs per uint2
    const float4* i4 = (const float4*)(inp + (size_t)row * NN);

    float4 x[8];
    float s = 0.f, q = 0.f;
    #pragma unroll
    for (int u = 0; u < 8; ++u) {
        const int idx = u * 32 + lane;        // float4 index within row (n = idx*4)
        uint2 hv = t2[idx];
        float2 f0 = __half22float2(*(__half2*)&hv.x);
        float2 f1 = __half22float2(*(__half2*)&hv.y);
        float4 r = i4[idx];
        x[u].x = f0.x + r.x; x[u].y = f0.y + r.y;
        x[u].z = f1.x + r.z; x[u].w = f1.y + r.w;
        s += x[u].x + x[u].y + x[u].z + x[u].w;
        q += x[u].x * x[u].x + x[u].y * x[u].y + x[u].z * x[u].z + x[u].w * x[u].w;
    }
    #pragma unroll
    for (int o = 16; o; o >>= 1) {
        s += __shfl_xor_sync(0xFFFFFFFFu, s, o);
        q += __shfl_xor_sync(0xFFFFFFFFu, q, o);
    }
    const float mu = s * (1.0f / (float)NN);
    const float var = q * (1.0f / (float)NN) - mu * mu;
    const float rs = rsqrtf(var + 1e-12f);

    float4* o4 = (float4*)(out + (size_t)row * NN);
    #pragma unroll
    for (int u = 0; u < 8; ++u) {
        const int idx = u * 32 + lane;
        const float4 g = ((const float4*)gamma)[idx];
        const float4 be = ((const float4*)beta)[idx];
        float4 v;
        v.x = g.x * (x[u].x - mu) * rs + be.x;
        v.y = g.y * (x[u].y - mu) * rs + be.y;
        v.z = g.z * (x[u].z - mu) * rs + be.z;
        v.w = g.w * (x[u].w - mu) * rs + be.w;
        o4[idx] = v;
    }
}

// ---------------- launch ----------------
extern "C" void kernel_launch(void* const* d_in, const int* in_sizes, int n_in,
                              void* d_out, int out_size) {
    (void)in_sizes; (void)n_in; (void)out_size;
    const float* hidden = (const float*)d_in[0];   // [16,512,4096]
    const float* input  = (const float*)d_in[1];   // [16,512,1024]
    const float* W      = (const float*)d_in[2];   // [1024,4096]
    const float* b      = (const float*)d_in[3];   // [1024]
    const float* gamma  = (const float*)d_in[4];   // [1024]
    const float* beta   = (const float*)d_in[5];   // [1024]
    float* out = (float*)d_out;

    cudaFuncSetAttribute(gemm_bin_kernel, cudaFuncAttributeMaxDynamicSharedMemorySize, SMEM_DYN);

    prep_kernel<<<NN + CONV_BLOCKS, 256>>>(W, hidden);
    gemm_bin_kernel<<<dim3(NN / BN, MM / BM), 256, SMEM_DYN>>>(b);
    ln_kernel<<<MM / LNROWS, 256>>>(input, gamma, beta, out);
}